// round 9
// baseline (speedup 1.0000x reference)
#include <cuda_runtime.h>
#include <math.h>
#include <stdint.h>

#define BS   128
#define GS   201
#define DIM  128
#define HALF 100
#define ROWS (BS*GS)            // 25728
#define OUTW (HALF + GS*GS)     // 40501
#define NPOS (GS*GS)            // 40401
#define NORMC 0.08838834764831845f  // 1/sqrt(128)

#define T_PER_B 316             // ceil(40401/128)
#define CHUNKS  3
#define TILES_PER_CHUNK 106

// ---------------- scratch (static device globals; no allocation) ----------------
__device__ float g_gproj[BS*DIM];
__device__ float g_h    [ROWS*DIM];
__device__ float g_hq   [ROWS*DIM];
__device__ float g_hk   [ROWS*DIM];
__device__ int   g_pre  [BS*GS];
__device__ int   g_post [BS*GS];
__device__ float g_qv   [BS*16*DIM];  // [b][s(4)][head(4)][128], norm folded in
__device__ float g_U    [ROWS*32];    // [b][i][32]
__device__ float g_V    [ROWS*32];    // [b][j][32]

// ---------------- helpers ----------------
__device__ __forceinline__ uint32_t tf32u(float x) {
    uint32_t r; asm("cvt.rna.tf32.f32 %0, %1;" : "=r"(r) : "f"(x)); return r;
}
// m16n8k8 tf32 MMA (portable PTX, HMMA path on sm_103)
__device__ __forceinline__ void mma8(float* c, const uint32_t* a, const uint32_t* b) {
    asm volatile(
        "mma.sync.aligned.m16n8k8.row.col.f32.tf32.tf32.f32 "
        "{%0,%1,%2,%3}, {%4,%5,%6,%7}, {%8,%9}, {%0,%1,%2,%3};"
        : "+f"(c[0]), "+f"(c[1]), "+f"(c[2]), "+f"(c[3])
        : "r"(a[0]), "r"(a[1]), "r"(a[2]), "r"(a[3]), "r"(b[0]), "r"(b[1]));
}

// ---------------- 1: per-batch prep: max->gproj, permutations, h_pick/h_del, qv ----------------
__global__ __launch_bounds__(256) void k_prepqv(
    const float* __restrict__ h_em, const int* __restrict__ rec,
    const float* __restrict__ Wg, const float* __restrict__ Wn,
    const int* __restrict__ fa,
    const float* __restrict__ Wq1, const float* __restrict__ Wk1,
    const float* __restrict__ Wq2, const float* __restrict__ Wk2) {
    int b = blockIdx.x, tid = threadIdx.x;
    int c = tid & 127, half = tid >> 7;
    __shared__ float red2[256];
    __shared__ float gmax[128], gpr[128], xp[128], xd[128], tp[128], td[128];

    // column max over nodes (split rows between halves)
    const float* pcol = h_em + (size_t)b*GS*DIM + c;
    float m = -INFINITY;
    for (int g = half; g < GS; g += 2) m = fmaxf(m, pcol[(size_t)g*DIM]);
    red2[tid] = m;
    // permutations
    for (int g = tid; g < GS; g += 256) {
        int r = rec[b*GS + g];
        g_pre[b*GS + r]  = g;
        g_post[b*GS + g] = rec[b*GS + r];
    }
    __syncthreads();
    if (tid < 128) gmax[tid] = fmaxf(red2[tid], red2[tid + 128]);
    __syncthreads();
    // gproj
    if (tid < 128) {
        float acc = 0.f;
        #pragma unroll 8
        for (int k = 0; k < 128; k++) acc = fmaf(gmax[k], Wg[k*128 + tid], acc);
        gpr[tid] = acc;
        g_gproj[b*128 + tid] = acc;
    }
    __syncthreads();
    // stage h_em rows for pick/del
    int pp = 1 + fa[b*3];
    int pdl = pp + HALF;
    red2[tid] = h_em[((size_t)b*GS + (half ? pdl : pp))*DIM + c];
    __syncthreads();
    // x = h_row @ Wn + gproj
    {
        float acc = gpr[c];
        const float* hr = &red2[half*128];
        #pragma unroll 8
        for (int d = 0; d < 128; d++) acc = fmaf(hr[d], Wn[d*128 + c], acc);
        if (half) xd[c] = acc; else xp[c] = acc;
    }
    __syncthreads();
    // per (mi, hd): t = Wq_h^T x ; qv = norm * Wk_h^T... (qv[c] = norm * sum_k Wk[c][k] t[k])
    int w = tid >> 5, l = tid & 31;
    for (int mi = 0; mi < 2; mi++) {
        const float* Wq = mi ? Wq2 : Wq1;
        const float* Wk = mi ? Wk2 : Wk1;
        for (int hd = 0; hd < 4; hd++) {
            const float* Wqs = Wq + (size_t)hd*128*128;
            const float* Wks = Wk + (size_t)hd*128*128;
            if (tid < 128) {
                float ap = 0.f, ad = 0.f;
                #pragma unroll 4
                for (int i = 0; i < 128; i++) {
                    float wv = Wqs[i*128 + tid];
                    ap = fmaf(xp[i], wv, ap);
                    ad = fmaf(xd[i], wv, ad);
                }
                tp[tid] = ap; td[tid] = ad;
            }
            __syncthreads();
            for (int rr = w; rr < 128; rr += 8) {
                float sp = 0.f, sd = 0.f;
                const float* row = Wks + rr*128;
                #pragma unroll
                for (int kk = l; kk < 128; kk += 32) {
                    float wv = row[kk];
                    sp = fmaf(tp[kk], wv, sp);
                    sd = fmaf(td[kk], wv, sd);
                }
                #pragma unroll
                for (int o = 16; o; o >>= 1) {
                    sp += __shfl_xor_sync(0xffffffffu, sp, o);
                    sd += __shfl_xor_sync(0xffffffffu, sd, o);
                }
                if (l == 0) {
                    g_qv[(((size_t)b*4 + mi    )*4 + hd)*128 + rr] = NORMC * sp;
                    g_qv[(((size_t)b*4 + mi + 2)*4 + hd)*128 + rr] = NORMC * sd;
                }
            }
            __syncthreads();
        }
    }
}

// ---------------- 2: h = h_em @ Wn + gproj ----------------
__global__ __launch_bounds__(256) void k_h(const float* __restrict__ A, const float* __restrict__ Wn) {
    __shared__ float As[64][33];
    __shared__ float Bs[32][DIM];
    int tid = threadIdx.x;
    int ty = tid >> 4, tx = tid & 15;
    int row0 = blockIdx.x * 64;
    float acc[4][8];
    #pragma unroll
    for (int i = 0; i < 4; i++)
        #pragma unroll
        for (int j = 0; j < 8; j++) acc[i][j] = 0.f;

    for (int kt = 0; kt < DIM; kt += 32) {
        for (int idx = tid; idx < 64*32; idx += 256) {
            int r = idx >> 5, k = idx & 31;
            As[r][k] = A[(size_t)(row0 + r)*DIM + kt + k];
        }
        for (int idx = tid; idx < 32*DIM; idx += 256) {
            int k = idx >> 7, c = idx & 127;
            Bs[k][c] = Wn[(kt + k)*DIM + c];
        }
        __syncthreads();
        #pragma unroll
        for (int k = 0; k < 32; k++) {
            float a[4], bb[8];
            #pragma unroll
            for (int i = 0; i < 4; i++) a[i] = As[ty*4 + i][k];
            #pragma unroll
            for (int j = 0; j < 8; j++) bb[j] = Bs[k][tx + j*16];
            #pragma unroll
            for (int i = 0; i < 4; i++)
                #pragma unroll
                for (int j = 0; j < 8; j++) acc[i][j] = fmaf(a[i], bb[j], acc[i][j]);
        }
        __syncthreads();
    }
    #pragma unroll
    for (int i = 0; i < 4; i++) {
        int row = row0 + ty*4 + i;
        int bi = row / GS;
        #pragma unroll
        for (int j = 0; j < 8; j++) {
            int col = tx + j*16;
            g_h[(size_t)row*DIM + col] = acc[i][j] + g_gproj[bi*DIM + col];
        }
    }
}

// ---------------- 3: U[b,i,:], V[b,j,:] ----------------
__global__ __launch_bounds__(256) void k_uv(const int* __restrict__ rec,
                                            const float* __restrict__ i_w1, const float* __restrict__ i_b1) {
    int b = blockIdx.y;
    int tid = threadIdx.x;
    int w = tid >> 5, l = tid & 31;
    __shared__ float w1s[16*32];
    __shared__ float b1s[32];
    for (int idx = tid; idx < 512; idx += 256) w1s[idx] = i_w1[idx];
    if (tid < 32) b1s[tid] = i_b1[tid];
    __syncthreads();
    int g = blockIdx.x * 8 + w;
    if (g >= GS) return;
    int rg = rec[b*GS + g];
    const float* hp  = g_h + ((size_t)b*GS + g )*DIM;
    const float* hnp = g_h + ((size_t)b*GS + rg)*DIM;
    float hg[4], hn[4];
    #pragma unroll
    for (int j = 0; j < 4; j++) { hg[j] = hp[l + 32*j]; hn[j] = hnp[l + 32*j]; }
    const float* qb = g_qv + (size_t)b*16*DIM;
    float cp[16];
    #pragma unroll
    for (int s = 0; s < 4; s++) {
        #pragma unroll
        for (int hd = 0; hd < 4; hd++) {
            const float* q = qb + (s*4 + hd)*DIM;
            float p = 0.f;
            #pragma unroll
            for (int j = 0; j < 4; j++) p = fmaf((s & 1) ? hn[j] : hg[j], q[l + 32*j], p);
            #pragma unroll
            for (int o = 16; o; o >>= 1) p += __shfl_xor_sync(0xffffffffu, p, o);
            cp[s*4 + hd] = p;
        }
    }
    float u = 0.f, v = b1s[l];
    #pragma unroll
    for (int f = 0; f < 8; f++) {
        u = fmaf(cp[f],     w1s[f*32 + l],       u);
        v = fmaf(cp[8 + f], w1s[(8 + f)*32 + l], v);
    }
    g_U[((size_t)b*GS + g)*32 + l] = u;
    g_V[((size_t)b*GS + g)*32 + l] = v;
}

// ---------------- 4: big (i,j) table via warp-level tf32 mma.sync (3-term split) ----------------
// K dimension permuted: fragment (kb, slot c) <-> original k = (c&3)*8 + (c>=4?4:0) + kb
// so each thread's needed k-values are contiguous (float4 loads). B permuted identically.
#define USTR 36
#define SM_U 0
#define SM_V (GS*USTR)
#define SM_B2 (2*GS*USTR)
#define SM_W3 (SM_B2 + 32)
#define SM_B3 (SM_W3 + 32)
#define SMEM_TABLE ((SM_B3 + 8) * 4)

__global__ __launch_bounds__(256, 2) void k_table(const float* __restrict__ i_w2, const float* __restrict__ i_b2,
                                                  const float* __restrict__ i_w3, const float* __restrict__ i_b3,
                                                  const unsigned char* __restrict__ mask,
                                                  float* __restrict__ out) {
    extern __shared__ float sm[];
    float* Us  = sm + SM_U;
    float* Vs  = sm + SM_V;
    float* b2s = sm + SM_B2;
    float* w3s = sm + SM_W3;
    float* b3s = sm + SM_B3;
    const int tid = threadIdx.x;
    const int w = tid >> 5, lane = tid & 31;
    const int gid = lane >> 2, tig = lane & 3;
    const int b = blockIdx.y;
    const int chunk = blockIdx.x;

    for (int idx = tid; idx < GS*32; idx += 256) {
        int r = idx >> 5, c = idx & 31;
        Us[r*USTR + c] = g_U[(size_t)b*GS*32 + idx];
        Vs[r*USTR + c] = g_V[(size_t)b*GS*32 + idx];
    }
    if (tid < 32) { b2s[tid] = i_b2[tid]; w3s[tid] = i_w3[tid]; }
    if (tid == 0) b3s[0] = i_b3[0];

    // B fragments with permuted K: row slot tig -> k = tig*8+kb, slot tig+4 -> k = tig*8+4+kb
    uint32_t bh[4][4][2], bl[4][4][2];
    #pragma unroll
    for (int kb = 0; kb < 4; kb++) {
        #pragma unroll
        for (int nb = 0; nb < 4; nb++) {
            float w0 = i_w2[(tig*8 + kb    )*32 + nb*8 + gid];
            float w1 = i_w2[(tig*8 + 4 + kb)*32 + nb*8 + gid];
            uint32_t h0 = tf32u(w0), h1 = tf32u(w1);
            bh[kb][nb][0] = h0; bh[kb][nb][1] = h1;
            bl[kb][nb][0] = tf32u(w0 - __uint_as_float(h0));
            bl[kb][nb][1] = tf32u(w1 - __uint_as_float(h1));
        }
    }
    __syncthreads();

    int t0 = chunk * TILES_PER_CHUNK;
    int t1 = min(t0 + TILES_PER_CHUNK, T_PER_B);

    for (int t = t0; t < t1; t++) {
        int gp0 = t*128 + w*16 + gid;          // row p0 (this thread's quad)
        int gq0 = min(gp0, NPOS - 1);
        int gq1 = min(gp0 + 8, NPOS - 1);
        int i0 = gq0 / GS, j0 = gq0 - i0*GS;
        int i1 = gq1 / GS, j1 = gq1 - i1*GS;

        // contiguous staging: thread needs k in [tig*8, tig*8+8)
        float4 U0a = *(const float4*)(Us + i0*USTR + tig*8);
        float4 U0b = *(const float4*)(Us + i0*USTR + tig*8 + 4);
        float4 V0a = *(const float4*)(Vs + j0*USTR + tig*8);
        float4 V0b = *(const float4*)(Vs + j0*USTR + tig*8 + 4);
        float4 U1a = *(const float4*)(Us + i1*USTR + tig*8);
        float4 U1b = *(const float4*)(Us + i1*USTR + tig*8 + 4);
        float4 V1a = *(const float4*)(Vs + j1*USTR + tig*8);
        float4 V1b = *(const float4*)(Vs + j1*USTR + tig*8 + 4);
        const float* u0a = (const float*)&U0a; const float* u0b = (const float*)&U0b;
        const float* v0a = (const float*)&V0a; const float* v0b = (const float*)&V0b;
        const float* u1a = (const float*)&U1a; const float* u1b = (const float*)&U1b;
        const float* v1a = (const float*)&V1a; const float* v1b = (const float*)&V1b;

        float C[4][4];
        #pragma unroll
        for (int nb = 0; nb < 4; nb++)
            #pragma unroll
            for (int q = 0; q < 4; q++) C[nb][q] = 0.f;

        #pragma unroll
        for (int kb = 0; kb < 4; kb++) {
            float a0 = fmaxf(u0a[kb] + v0a[kb], 0.f);   // (p0, k=tig*8+kb)
            float a1 = fmaxf(u1a[kb] + v1a[kb], 0.f);   // (p1, k=tig*8+kb)
            float a2 = fmaxf(u0b[kb] + v0b[kb], 0.f);   // (p0, k=tig*8+4+kb)
            float a3 = fmaxf(u1b[kb] + v1b[kb], 0.f);   // (p1, k=tig*8+4+kb)
            uint32_t ah[4], al[4];
            ah[0] = tf32u(a0); al[0] = tf32u(a0 - __uint_as_float(ah[0]));
            ah[1] = tf32u(a1); al[1] = tf32u(a1 - __uint_as_float(ah[1]));
            ah[2] = tf32u(a2); al[2] = tf32u(a2 - __uint_as_float(ah[2]));
            ah[3] = tf32u(a3); al[3] = tf32u(a3 - __uint_as_float(ah[3]));
            #pragma unroll
            for (int nb = 0; nb < 4; nb++) {
                mma8(C[nb], ah, bh[kb][nb]);
                mma8(C[nb], al, bh[kb][nb]);
                mma8(C[nb], ah, bl[kb][nb]);
            }
        }

        // layer-3 epilogue in registers
        float y0 = 0.f, y1 = 0.f;
        #pragma unroll
        for (int nb = 0; nb < 4; nb++) {
            int m = nb*8 + 2*tig;
            float b2a = b2s[m], b2b = b2s[m + 1];
            float w3a = w3s[m], w3b = w3s[m + 1];
            y0 += fmaxf(C[nb][0] + b2a, 0.f)*w3a + fmaxf(C[nb][1] + b2b, 0.f)*w3b;
            y1 += fmaxf(C[nb][2] + b2a, 0.f)*w3a + fmaxf(C[nb][3] + b2b, 0.f)*w3b;
        }
        y0 += __shfl_xor_sync(0xffffffffu, y0, 1);
        y0 += __shfl_xor_sync(0xffffffffu, y0, 2);
        y1 += __shfl_xor_sync(0xffffffffu, y1, 1);
        y1 += __shfl_xor_sync(0xffffffffu, y1, 2);

        if (tig == 0) {
            float b3 = b3s[0];
            if (gp0 < NPOS) {
                float vv = tanhf(y0 + b3) * 6.f;
                if (mask[(size_t)b*NPOS + gp0]) vv = -1e20f;
                out[(size_t)b*OUTW + HALF + gp0] = vv;
            }
            int gpB = gp0 + 8;
            if (gpB < NPOS) {
                float vv = tanhf(y1 + b3) * 6.f;
                if (mask[(size_t)b*NPOS + gpB]) vv = -1e20f;
                out[(size_t)b*OUTW + HALF + gpB] = vv;
            }
        }
    }
}

// ---------------- 5: HQ/HK projections (kd=32 heads) ----------------
__global__ __launch_bounds__(256) void k_hqk(const float* __restrict__ WQr, const float* __restrict__ WKr) {
    __shared__ float As[64][33];
    __shared__ float Bq[32][DIM];
    __shared__ float Bk[32][DIM];
    int tid = threadIdx.x;
    int ty = tid >> 4, tx = tid & 15;
    int row0 = blockIdx.x * 64;
    float accq[4][8], acck[4][8];
    #pragma unroll
    for (int i = 0; i < 4; i++)
        #pragma unroll
        for (int j = 0; j < 8; j++) { accq[i][j] = 0.f; acck[i][j] = 0.f; }

    for (int kt = 0; kt < DIM; kt += 32) {
        for (int idx = tid; idx < 64*32; idx += 256) {
            int r = idx >> 5, k = idx & 31;
            As[r][k] = g_h[(size_t)(row0 + r)*DIM + kt + k];
        }
        for (int idx = tid; idx < 32*DIM; idx += 256) {
            int k = idx >> 7, n = idx & 127;
            int hh = n >> 5, c = n & 31;
            int gidx = (hh*DIM + kt + k)*32 + c;
            Bq[k][n] = WQr[gidx];
            Bk[k][n] = WKr[gidx];
        }
        __syncthreads();
        #pragma unroll
        for (int k = 0; k < 32; k++) {
            float a[4], bq[8], bk[8];
            #pragma unroll
            for (int i = 0; i < 4; i++) a[i] = As[ty*4 + i][k];
            #pragma unroll
            for (int j = 0; j < 8; j++) { bq[j] = Bq[k][tx + j*16]; bk[j] = Bk[k][tx + j*16]; }
            #pragma unroll
            for (int i = 0; i < 4; i++)
                #pragma unroll
                for (int j = 0; j < 8; j++) {
                    accq[i][j] = fmaf(a[i], bq[j], accq[i][j]);
                    acck[i][j] = fmaf(a[i], bk[j], acck[i][j]);
                }
        }
        __syncthreads();
    }
    #pragma unroll
    for (int i = 0; i < 4; i++) {
        int row = row0 + ty*4 + i;
        #pragma unroll
        for (int j = 0; j < 8; j++) {
            int col = tx + j*16;
            g_hq[(size_t)row*DIM + col] = accq[i][j];
            g_hk[(size_t)row*DIM + col] = acck[i][j];
        }
    }
}

// ---------------- 6: removal table ----------------
__global__ void k_removal(const float* __restrict__ sel,
                          const float* __restrict__ rw1, const float* __restrict__ rb1,
                          const float* __restrict__ rw2, const float* __restrict__ rb2,
                          const float* __restrict__ rw3, const float* __restrict__ rb3,
                          float* __restrict__ out) {
    int b = blockIdx.x, i = threadIdx.x;
    __shared__ float w1s[12*32], b1s[32], w2s[32*32], b2s[32], w3s[32];
    for (int idx = i; idx < 12*32; idx += 128) w1s[idx] = rw1[idx];
    for (int idx = i; idx < 32*32; idx += 128) w2s[idx] = rw2[idx];
    if (i < 32) { b1s[i] = rb1[i]; b2s[i] = rb2[i]; w3s[i] = rw3[i]; }
    __syncthreads();
    if (i >= HALF) return;
    float feat[12];
    #pragma unroll
    for (int k8 = 0; k8 < 8; k8++) {
        int hd = k8 & 3;
        int g = (k8 < 4) ? (1 + i) : (1 + HALF + i);
        int gp = g_pre[b*GS + g], gq = g_post[b*GS + g];
        const float* qp = g_hq + ((size_t)b*GS + gp)*DIM + hd*32;
        const float* qg = g_hq + ((size_t)b*GS + g )*DIM + hd*32;
        const float* kg = g_hk + ((size_t)b*GS + g )*DIM + hd*32;
        const float* kq = g_hk + ((size_t)b*GS + gq)*DIM + hd*32;
        float s = 0.f;
        #pragma unroll
        for (int c = 0; c < 32; c++) s += qp[c]*kg[c] + qg[c]*kq[c] - qp[c]*kq[c];
        feat[k8] = s;
    }
    #pragma unroll
    for (int c = 0; c < 4; c++) feat[8 + c] = sel[((size_t)b*4 + c)*HALF + i];
    float x1[32];
    #pragma unroll
    for (int m = 0; m < 32; m++) {
        float a = b1s[m];
        #pragma unroll
        for (int f = 0; f < 12; f++) a = fmaf(feat[f], w1s[f*32 + m], a);
        x1[m] = fmaxf(a, 0.f);
    }
    float y = rb3[0];
    #pragma unroll
    for (int m = 0; m < 32; m++) {
        float a = b2s[m];
        #pragma unroll
        for (int k = 0; k < 32; k++) a = fmaf(x1[k], w2s[k*32 + m], a);
        y = fmaf(fmaxf(a, 0.f), w3s[m], y);
    }
    out[(size_t)b*OUTW + i] = tanhf(y) * 6.f;
}

// ---------------- 7: in-place softmax; exp cached in pass 2 ----------------
template <int NT>
__global__ void k_softmax(float* __restrict__ out, int off, int n) {
    int b = blockIdx.x, tid = threadIdx.x;
    float* p = out + (size_t)b*OUTW + off;
    __shared__ float red[NT];
    __shared__ float sv[2];
    float m = -INFINITY;
    for (int idx = tid; idx < n; idx += NT) m = fmaxf(m, p[idx]);
    red[tid] = m; __syncthreads();
    for (int o = NT/2; o; o >>= 1) { if (tid < o) red[tid] = fmaxf(red[tid], red[tid + o]); __syncthreads(); }
    if (tid == 0) sv[0] = red[0];
    __syncthreads();
    float mx = sv[0];
    float s = 0.f;
    for (int idx = tid; idx < n; idx += NT) {
        float e = __expf(p[idx] - mx);
        p[idx] = e;
        s += e;
    }
    red[tid] = s; __syncthreads();
    for (int o = NT/2; o; o >>= 1) { if (tid < o) red[tid] += red[tid + o]; __syncthreads(); }
    if (tid == 0) sv[1] = 1.f / red[0];
    __syncthreads();
    float inv = sv[1];
    for (int idx = tid; idx < n; idx += NT) p[idx] *= inv;
}

// ---------------- launch ----------------
extern "C" void kernel_launch(void* const* d_in, const int* in_sizes, int n_in,
                              void* d_out, int out_size) {
    const float* h_em = (const float*)d_in[0];
    const float* sel  = (const float*)d_in[1];
    const float* Wn   = (const float*)d_in[2];
    const float* Wg   = (const float*)d_in[3];
    const float* WQr  = (const float*)d_in[4];
    const float* WKr  = (const float*)d_in[5];
    const float* rw1  = (const float*)d_in[6];
    const float* rb1  = (const float*)d_in[7];
    const float* rw2  = (const float*)d_in[8];
    const float* rb2  = (const float*)d_in[9];
    const float* rw3  = (const float*)d_in[10];
    const float* rb3  = (const float*)d_in[11];
    const float* Wq1  = (const float*)d_in[12];
    const float* Wk1  = (const float*)d_in[13];
    const float* Wq2  = (const float*)d_in[14];
    const float* Wk2  = (const float*)d_in[15];
    const float* iw1  = (const float*)d_in[16];
    const float* ib1  = (const float*)d_in[17];
    const float* iw2  = (const float*)d_in[18];
    const float* ib2  = (const float*)d_in[19];
    const float* iw3  = (const float*)d_in[20];
    const float* ib3  = (const float*)d_in[21];
    const int*   rec  = (const int*)d_in[22];
    const int*   fa   = (const int*)d_in[23];
    const unsigned char* mask = (const unsigned char*)d_in[24];
    float* out = (float*)d_out;

    cudaFuncSetAttribute(k_table, cudaFuncAttributeMaxDynamicSharedMemorySize, SMEM_TABLE);

    k_prepqv <<<BS, 256>>>(h_em, rec, Wg, Wn, fa, Wq1, Wk1, Wq2, Wk2);   // idx 0
    k_h      <<<ROWS/64, 256>>>(h_em, Wn);                                // idx 1
    k_uv     <<<dim3(26, BS), 256>>>(rec, iw1, ib1);                      // idx 2
    k_table  <<<dim3(CHUNKS, BS), 256, SMEM_TABLE>>>(iw2, ib2, iw3, ib3, mask, out); // idx 3 (profiled)
    k_hqk    <<<ROWS/64, 256>>>(WQr, WKr);                                // idx 4
    k_removal<<<BS, 128>>>(sel, rw1, rb1, rw2, rb2, rw3, rb3, out);       // idx 5
    k_softmax<128> <<<BS, 128>>>(out, 0, HALF);                           // idx 6
    k_softmax<1024><<<BS, 1024>>>(out, HALF, GS*GS);                      // idx 7
}